// round 16
// baseline (speedup 1.0000x reference)
#include <cuda_runtime.h>
#include <cuda_bf16.h>

// FinDiffNonUniform: yd[i,b] = sum_s w[i,s] * y[i + off[i,s], b]
// N=8192, B=4096, S=7, fp32.
//
// R16 FINAL (stability confirmation of the R15 winner, bench 45.6us).
// Measured optimum of the session-wide search:
//   - front-batched 16-row register window (max MLP; beats rolling/ring/TMA)
//   - float2 lanes (beats float1/float4), TPB=256 (beats 128)
//   - TR=10 rows/CTA (TR curve: 8->42.1, 10->41.9, 12->41.3, 14->43.0,
//     16->44.2 us kernel; TR=10 best on bench), 40 regs, 6 CTAs/SM
//   - row-tiles on blockIdx.x (fast axis): scheduling-adjacent CTAs share
//     L2-hot halo lines (-3.2us vs column-fast)
// Kernel is DRAM-stream bound at ~5.3 TB/s with near-compulsory bytes
// (134MB writes + ~86MB read fills; y exceeds the 126MB L2).
// Interior tiles verify offsets == s-3 at runtime; boundary/non-centered
// tiles take a generic gather path; arbitrary shapes a scalar fallback.

#define S_W 7
#define TR 10
#define TPB 256
#define VEC 2
#define WIN (TR + 6)               // 16-row window
#define COLS_PER_BLOCK (TPB * VEC)

__global__ __launch_bounds__(TPB, 6)
void findiff_final_kernel(const float* __restrict__ y,
                          const float* __restrict__ coef,
                          const int* __restrict__ offs,
                          float* __restrict__ out,
                          int N, int B)
{
    __shared__ float s_w[TR * S_W];
    __shared__ int   s_o[TR * S_W];
    __shared__ int   s_centered;

    const int t  = threadIdx.x;
    const int i0 = blockIdx.x * TR;            // row tile on FAST axis

    if (t == 0) s_centered = 1;
    __syncthreads();

    if (t < TR * S_W) {
        const int gidx = i0 * S_W + t;
        if (gidx < N * S_W) {
            s_w[t] = __ldg(&coef[gidx]);
            const int o = __ldg(&offs[gidx]);
            s_o[t] = o;
            if (o != (t % S_W) - 3) s_centered = 0;
        } else {
            s_w[t] = 0.0f;
            s_o[t] = 0;
        }
    }
    __syncthreads();

    const int col = blockIdx.y * COLS_PER_BLOCK + t * VEC;
    if (col >= B) return;

    const bool interior = (i0 >= 3) && (i0 + TR + 2 <= N - 1) && s_centered;

    if (interior) {
        // ---- fast path: front-batched register window, offsets = s-3 ----
        float2 win[WIN];
        const float* base = y + (size_t)(i0 - 3) * (size_t)B + col;
        #pragma unroll
        for (int k = 0; k < WIN; ++k)
            win[k] = *reinterpret_cast<const float2*>(base + (size_t)k * (size_t)B);

        float* obase = out + (size_t)i0 * (size_t)B + col;
        #pragma unroll
        for (int r = 0; r < TR; ++r) {
            float2 acc = make_float2(0.f, 0.f);
            #pragma unroll
            for (int s = 0; s < S_W; ++s) {
                const float  w = s_w[r * S_W + s];
                const float2 v = win[r + s];
                acc.x = fmaf(w, v.x, acc.x);
                acc.y = fmaf(w, v.y, acc.y);
            }
            *reinterpret_cast<float2*>(obase + (size_t)r * (size_t)B) = acc;
        }
    } else {
        // ---- generic path: boundary / partial / non-centered tiles ----
        #pragma unroll
        for (int r = 0; r < TR; ++r) {
            const int i = i0 + r;
            if (i >= N) break;
            float2 acc = make_float2(0.f, 0.f);
            #pragma unroll
            for (int s = 0; s < S_W; ++s) {
                const float w = s_w[r * S_W + s];
                const int   j = i + s_o[r * S_W + s];
                const float2 v = *reinterpret_cast<const float2*>(
                    y + (size_t)j * (size_t)B + col);
                acc.x = fmaf(w, v.x, acc.x);
                acc.y = fmaf(w, v.y, acc.y);
            }
            *reinterpret_cast<float2*>(out + (size_t)i * (size_t)B + col) = acc;
        }
    }
}

// Fully generic scalar fallback (any N, B).
__global__ void findiff_scalar_kernel(const float* __restrict__ y,
                                      const float* __restrict__ coef,
                                      const int* __restrict__ offs,
                                      float* __restrict__ out,
                                      int N, int B)
{
    const long long total = (long long)N * B;
    for (long long idx = (long long)blockIdx.x * blockDim.x + threadIdx.x;
         idx < total;
         idx += (long long)gridDim.x * blockDim.x) {
        const int i = (int)(idx / B);
        const int b = (int)(idx % B);
        float acc = 0.f;
        #pragma unroll
        for (int s = 0; s < S_W; ++s) {
            const float w = coef[i * S_W + s];
            const int   j = i + offs[i * S_W + s];
            acc = fmaf(w, y[(size_t)j * (size_t)B + b], acc);
        }
        out[idx] = acc;
    }
}

extern "C" void kernel_launch(void* const* d_in, const int* in_sizes, int n_in,
                              void* d_out, int out_size)
{
    const float* y    = (const float*)d_in[0];
    const float* coef = (const float*)d_in[1];
    const int*   offs = (const int*)d_in[2];
    float* out = (float*)d_out;

    const int N = in_sizes[1] / S_W;       // all_coefficients is [N, 7]
    const int B = in_sizes[0] / N;         // y is [N, B]

    if ((B % COLS_PER_BLOCK) == 0) {
        dim3 grid((N + TR - 1) / TR, B / COLS_PER_BLOCK);
        findiff_final_kernel<<<grid, TPB>>>(y, coef, offs, out, N, B);
    } else {
        const long long total = (long long)N * B;
        int blocks = (int)((total + 255) / 256);
        if (blocks > 65535 * 32) blocks = 65535 * 32;
        findiff_scalar_kernel<<<blocks, 256>>>(y, coef, offs, out, N, B);
    }
}